// round 2
// baseline (speedup 1.0000x reference)
#include <cuda_runtime.h>
#include <cstdint>

#define NB 64      // batch
#define UD 512     // latent units
#define ED 512     // embedding dim
#define VD 32000   // vocab
#define TS 20      // decode steps
#define ZN 2048    // 4*U
#define KSPL 8     // K-splits for gate GEMM

// ---- persistent scratch (device globals: allocation-free) ----
__device__ float g_h[NB * UD];
__device__ float g_c[NB * UD];
__device__ float g_zpart[KSPL][NB * ZN];        // K-split partials for gate GEMM
__device__ unsigned long long g_amax[NB];       // encoded (value, ~index) per row

// sortable encoding: higher key = larger float; tie -> lower column index wins
__device__ __forceinline__ unsigned long long enc_max(float v, int col) {
    unsigned int u = __float_as_uint(v);
    unsigned int key = (u & 0x80000000u) ? ~u : (u | 0x80000000u);
    return ((unsigned long long)key << 32) |
           (unsigned long long)(0xFFFFFFFFu - (unsigned int)col);
}

// ---- packed fp32x2 helpers (Blackwell): 2 fp32 FMAs per issue slot ----
__device__ __forceinline__ void ffma2(unsigned long long& d,
                                      unsigned long long a,
                                      unsigned long long b) {
    asm("fma.rn.f32x2 %0, %1, %2, %0;" : "+l"(d) : "l"(a), "l"(b));
}
__device__ __forceinline__ unsigned long long dup2(float x) {
    unsigned long long r;
    asm("mov.b64 %0, {%1, %1};" : "=l"(r) : "r"(__float_as_uint(x)));
    return r;
}
__device__ __forceinline__ float2 unpack2(unsigned long long p) {
    unsigned int lo, hi;
    asm("mov.b64 {%0, %1}, %2;" : "=r"(lo), "=r"(hi) : "l"(p));
    return make_float2(__uint_as_float(lo), __uint_as_float(hi));
}

// ============================================================================
// Kernel A1: z_part[ks] = A_chunk @ W_chunk  (M=64, N=2048, K=1024 split by 8)
//   A = concat(emb_table[idx], h_prev). grid (64 n-tiles x 8 ksplit), 256 thr.
//   Register-double-buffered tiles; packed FFMA2 inner loop.
// ============================================================================
__global__ void __launch_bounds__(256) lstm_gemm_kernel(
    const float* __restrict__ h0, const float* __restrict__ emb,
    const float* __restrict__ Wx, const float* __restrict__ Wh, int t)
{
    const int ks  = blockIdx.y;          // 0..7 (0-3 = x-part, 4-7 = h-part)
    const int n0  = blockIdx.x * 32;
    const int tid = threadIdx.x;

    __shared__ float sA[32][68];         // [k][m], row stride 272B (16B mult)
    __shared__ float sB[32][32];
    __shared__ const float* rowptr[NB];

    const bool xpart = (ks < 4);
    const int  kbase = (ks & 3) * 128;

    if (tid < NB) {
        if (xpart) {
            int idx = 1; // GO token
            if (t != 0)
                idx = (int)(0xFFFFFFFFu - (unsigned int)(g_amax[tid] & 0xFFFFFFFFull));
            rowptr[tid] = emb + (size_t)idx * ED + kbase;
        } else {
            const float* hp = (t == 0) ? h0 : g_h;
            rowptr[tid] = hp + tid * UD + kbase;
        }
    }
    __syncthreads();

    const float* Wsrc = xpart ? Wx : Wh;

    unsigned long long acc2[4];          // 4 m-pairs x 1 col
#pragma unroll
    for (int i = 0; i < 4; i++) acc2[i] = 0ull;

    const int mm = (tid & 7) * 8;        // 8 M-rows per thread (4 pairs)
    const int nn = tid >> 3;             // 1 N-col per thread

    float ra[8], rw[4];
    // prefetch tile 0
#pragma unroll
    for (int i = 0; i < 8; i++) {
        int lin = tid + i * 256;
        ra[i] = rowptr[lin >> 5][lin & 31];
    }
#pragma unroll
    for (int i = 0; i < 4; i++) {
        int lin = tid + i * 256;
        rw[i] = Wsrc[(size_t)(kbase + (lin >> 5)) * ZN + n0 + (lin & 31)];
    }

    for (int tile = 0; tile < 4; tile++) {
        const int kt = tile * 32;
#pragma unroll
        for (int i = 0; i < 8; i++) {
            int lin = tid + i * 256;
            sA[lin & 31][lin >> 5] = ra[i];
        }
#pragma unroll
        for (int i = 0; i < 4; i++) {
            int lin = tid + i * 256;
            sB[lin >> 5][lin & 31] = rw[i];
        }
        __syncthreads();
        if (tile < 3) {
            const int ktn = kt + 32;
#pragma unroll
            for (int i = 0; i < 8; i++) {
                int lin = tid + i * 256;
                ra[i] = rowptr[lin >> 5][ktn + (lin & 31)];
            }
#pragma unroll
            for (int i = 0; i < 4; i++) {
                int lin = tid + i * 256;
                rw[i] = Wsrc[(size_t)(kbase + ktn + (lin >> 5)) * ZN + n0 + (lin & 31)];
            }
        }
#pragma unroll
        for (int k = 0; k < 32; k++) {
            unsigned long long bdup = dup2(sB[k][nn]);
            const ulonglong2* ap0 = (const ulonglong2*)&sA[k][mm];
            const ulonglong2* ap1 = (const ulonglong2*)&sA[k][mm + 4];
            ulonglong2 p0 = *ap0;
            ulonglong2 p1 = *ap1;
            ffma2(acc2[0], p0.x, bdup);
            ffma2(acc2[1], p0.y, bdup);
            ffma2(acc2[2], p1.x, bdup);
            ffma2(acc2[3], p1.y, bdup);
        }
        __syncthreads();
    }
#pragma unroll
    for (int p = 0; p < 4; p++) {
        float2 v = unpack2(acc2[p]);
        g_zpart[ks][(size_t)(mm + 2 * p)     * ZN + n0 + nn] = v.x;
        g_zpart[ks][(size_t)(mm + 2 * p + 1) * ZN + n0 + nn] = v.y;
    }
}

// ============================================================================
// Kernel A2: sum partials + bias -> gates -> update h,c; reset argmax buffer.
// ============================================================================
__global__ void __launch_bounds__(256) lstm_update_kernel(
    const float* __restrict__ c0, const float* __restrict__ b_lstm, int t)
{
    int id = blockIdx.x * blockDim.x + threadIdx.x;
    if (blockIdx.x == 0 && threadIdx.x < NB) g_amax[threadIdx.x] = 0ull;
    if (id >= NB * UD) return;

    int b = id / UD;
    int u = id % UD;
    size_t base = (size_t)b * ZN;

    float zi = 0.f, zf = 0.f, zg = 0.f, zo = 0.f;
#pragma unroll
    for (int ks = 0; ks < KSPL; ks++) {
        zi += g_zpart[ks][base + u];
        zf += g_zpart[ks][base + 512 + u];
        zg += g_zpart[ks][base + 1024 + u];
        zo += g_zpart[ks][base + 1536 + u];
    }
    zi += b_lstm[u];        zf += b_lstm[512 + u];
    zg += b_lstm[1024 + u]; zo += b_lstm[1536 + u];

    float cp = (t == 0) ? c0[id] : g_c[id];
    // accurate (not __expf): argmax flips from gate noise are catastrophic
    float si = 1.f / (1.f + expf(-zi));
    float sf = 1.f / (1.f + expf(-zf));
    float so = 1.f / (1.f + expf(-zo));
    float tg = tanhf(zg);
    float cn = sf * cp + si * tg;
    float hn = so * tanhf(cn);
    g_c[id] = cn;
    g_h[id] = hn;
}

// ============================================================================
// Kernel B: logits = h @ Wd + bd  (M=64, N=32000, K=512), write out + argmax.
//   grid 500 (64-col tiles), 256 thr, thread tile 8M(4 pairs) x 2N, FFMA2,
//   register-double-buffered K tiles.
// ============================================================================
__global__ void __launch_bounds__(256) logits_kernel(
    const float* __restrict__ Wd, const float* __restrict__ bd,
    float* __restrict__ out, int t)
{
    const int tid = threadIdx.x;
    const int v0  = blockIdx.x * 64;

    __shared__ float sA[32][68];     // [k][m], padded (272B rows, 16B-aligned)
    __shared__ float sB[32][64];     // [k][n]

    unsigned long long acc2[4][2];   // 4 m-pairs x 2 n-cols
#pragma unroll
    for (int i = 0; i < 4; i++) { acc2[i][0] = 0ull; acc2[i][1] = 0ull; }

    const int m0 = (tid >> 5) * 8;   // warp -> 8 rows
    const int nc = (tid & 31) * 2;   // lane -> 2 cols

    float ra[8], rb[8];
    // prefetch tile 0
#pragma unroll
    for (int i = 0; i < 8; i++) {
        int lin = tid + i * 256;
        ra[i] = g_h[(lin >> 5) * UD + (lin & 31)];
    }
#pragma unroll
    for (int i = 0; i < 8; i++) {
        int lin = tid + i * 256;
        rb[i] = Wd[(size_t)(lin >> 6) * VD + v0 + (lin & 63)];
    }

    for (int tile = 0; tile < 16; tile++) {
        const int kt = tile * 32;
#pragma unroll
        for (int i = 0; i < 8; i++) {
            int lin = tid + i * 256;
            sA[lin & 31][lin >> 5] = ra[i];
        }
#pragma unroll
        for (int i = 0; i < 8; i++) {
            int lin = tid + i * 256;
            sB[lin >> 6][lin & 63] = rb[i];
        }
        __syncthreads();
        if (tile < 15) {
            const int ktn = kt + 32;
#pragma unroll
            for (int i = 0; i < 8; i++) {
                int lin = tid + i * 256;
                ra[i] = g_h[(lin >> 5) * UD + ktn + (lin & 31)];
            }
#pragma unroll
            for (int i = 0; i < 8; i++) {
                int lin = tid + i * 256;
                rb[i] = Wd[(size_t)(ktn + (lin >> 6)) * VD + v0 + (lin & 63)];
            }
        }
#pragma unroll
        for (int k = 0; k < 32; k++) {
            float2 bv = *(const float2*)&sB[k][nc];
            unsigned long long b0 = dup2(bv.x);
            unsigned long long b1 = dup2(bv.y);
            ulonglong2 p0 = *(const ulonglong2*)&sA[k][m0];
            ulonglong2 p1 = *(const ulonglong2*)&sA[k][m0 + 4];
            ffma2(acc2[0][0], p0.x, b0); ffma2(acc2[0][1], p0.x, b1);
            ffma2(acc2[1][0], p0.y, b0); ffma2(acc2[1][1], p0.y, b1);
            ffma2(acc2[2][0], p1.x, b0); ffma2(acc2[2][1], p1.x, b1);
            ffma2(acc2[3][0], p1.y, b0); ffma2(acc2[3][1], p1.y, b1);
        }
        __syncthreads();
    }

    float2 bias = *(const float2*)&bd[v0 + nc];

    unsigned long long best[8];
#pragma unroll
    for (int p = 0; p < 4; p++) {
        float2 c0v = unpack2(acc2[p][0]);   // (row 2p, col nc), (row 2p+1, col nc)
        float2 c1v = unpack2(acc2[p][1]);   // (row 2p, col nc+1), (row 2p+1, col nc+1)
        int mlo = m0 + 2 * p;
        int mhi = mlo + 1;
        float2 rlo = make_float2(c0v.x + bias.x, c1v.x + bias.y);
        float2 rhi = make_float2(c0v.y + bias.x, c1v.y + bias.y);
        *(float2*)&out[((size_t)mlo * TS + t) * VD + v0 + nc] = rlo;
        *(float2*)&out[((size_t)mhi * TS + t) * VD + v0 + nc] = rhi;

        unsigned long long e = enc_max(rlo.x, v0 + nc);
        unsigned long long e2 = enc_max(rlo.y, v0 + nc + 1); if (e2 > e) e = e2;
        best[2 * p] = e;
        e = enc_max(rhi.x, v0 + nc);
        e2 = enc_max(rhi.y, v0 + nc + 1); if (e2 > e) e = e2;
        best[2 * p + 1] = e;
    }
    // warp-level max per row (32 lanes cover all 64 cols of rows m0..m0+7)
#pragma unroll
    for (int off = 16; off > 0; off >>= 1) {
#pragma unroll
        for (int i = 0; i < 8; i++) {
            unsigned long long o = __shfl_xor_sync(0xFFFFFFFFu, best[i], off);
            if (o > best[i]) best[i] = o;
        }
    }
    if ((tid & 31) == 0) {
#pragma unroll
        for (int i = 0; i < 8; i++)
            atomicMax(&g_amax[m0 + i], best[i]);
    }
}

// ============================================================================
extern "C" void kernel_launch(void* const* d_in, const int* in_sizes, int n_in,
                              void* d_out, int out_size)
{
    const float* h0  = (const float*)d_in[0];
    const float* c0  = (const float*)d_in[1];
    const float* emb = (const float*)d_in[2];
    const float* Wx  = (const float*)d_in[3];
    const float* Wh  = (const float*)d_in[4];
    const float* bl  = (const float*)d_in[5];
    const float* Wd  = (const float*)d_in[6];
    const float* bd  = (const float*)d_in[7];
    float* out = (float*)d_out;

    for (int t = 0; t < TS; t++) {
        dim3 g1(64, KSPL);
        lstm_gemm_kernel<<<g1, 256>>>(h0, emb, Wx, Wh, t);
        lstm_update_kernel<<<128, 256>>>(c0, bl, t);
        logits_kernel<<<500, 256>>>(Wd, bd, out, t);
    }
}

// round 4
// speedup vs baseline: 4.7908x; 4.7908x over previous
#include <cuda_runtime.h>
#include <cuda_bf16.h>
#include <cstdint>

#define NB 64
#define UD 512
#define VD 32000
#define TS 20
#define ZN 2048
#define GK 1024
#define GKS 4          // gate K-splits (grid.y)

// ---------------- persistent device scratch ----------------
__device__ float g_h[NB * UD];
__device__ float g_c[NB * UD];
__device__ float g_zpart[GKS][NB * ZN];
__device__ unsigned long long g_amax[NB];
__device__ __nv_bfloat16 g_Wd0[(size_t)UD * VD];
__device__ __nv_bfloat16 g_Wd1[(size_t)UD * VD];
__device__ __nv_bfloat16 g_Wg0[(size_t)GK * ZN];
__device__ __nv_bfloat16 g_Wg1[(size_t)GK * ZN];
__device__ __nv_bfloat16 g_Ag0[NB * GK];
__device__ __nv_bfloat16 g_Ag1[NB * GK];
__device__ __nv_bfloat16 g_Al0[NB * UD];
__device__ __nv_bfloat16 g_Al1[NB * UD];

// ---------------- helpers ----------------
__device__ __forceinline__ unsigned long long enc_max(float v, int col) {
    unsigned int u = __float_as_uint(v);
    unsigned int key = (u & 0x80000000u) ? ~u : (u | 0x80000000u);
    return ((unsigned long long)key << 32) |
           (unsigned long long)(0xFFFFFFFFu - (unsigned int)col);
}
__device__ __forceinline__ int dec_idx(unsigned long long e) {
    return (int)(0xFFFFFFFFu - (unsigned int)(e & 0xFFFFFFFFull));
}
__device__ __forceinline__ void split2(float v, __nv_bfloat16& b0, __nv_bfloat16& b1) {
    b0 = __float2bfloat16(v);
    b1 = __float2bfloat16(v - __bfloat162float(b0));
}
__device__ __forceinline__ uint32_t smem_u32(const void* p) {
    uint32_t a;
    asm("{ .reg .u64 t; cvta.to.shared.u64 t, %1; cvt.u32.u64 %0, t; }"
        : "=r"(a) : "l"(p));
    return a;
}
__device__ __forceinline__ void cp16(uint32_t dst, const void* src) {
    asm volatile("cp.async.cg.shared.global [%0], [%1], 16;" :: "r"(dst), "l"(src));
}
#define CP_COMMIT() asm volatile("cp.async.commit_group;" ::: "memory")
#define CP_WAIT(n)  asm volatile("cp.async.wait_group %0;" :: "n"(n) : "memory")

__device__ __forceinline__ void ldm_x4(uint32_t* r, uint32_t addr) {
    asm volatile("ldmatrix.sync.aligned.m8n8.x4.shared.b16 {%0,%1,%2,%3}, [%4];"
        : "=r"(r[0]), "=r"(r[1]), "=r"(r[2]), "=r"(r[3]) : "r"(addr));
}
__device__ __forceinline__ void ldm_x4t(uint32_t* r, uint32_t addr) {
    asm volatile("ldmatrix.sync.aligned.m8n8.x4.trans.shared.b16 {%0,%1,%2,%3}, [%4];"
        : "=r"(r[0]), "=r"(r[1]), "=r"(r[2]), "=r"(r[3]) : "r"(addr));
}
__device__ __forceinline__ void mma16816(float* c, const uint32_t* a, const uint32_t* b) {
    asm volatile(
        "mma.sync.aligned.m16n8k16.row.col.f32.bf16.bf16.f32 "
        "{%0,%1,%2,%3}, {%4,%5,%6,%7}, {%8,%9}, {%0,%1,%2,%3};"
        : "+f"(c[0]), "+f"(c[1]), "+f"(c[2]), "+f"(c[3])
        : "r"(a[0]), "r"(a[1]), "r"(a[2]), "r"(a[3]), "r"(b[0]), "r"(b[1]));
}

// ============================================================================
// one-time weight splits (bf16 hi/lo), plain row-major
// ============================================================================
__global__ void __launch_bounds__(256) prep_Wd_kernel(const float* __restrict__ Wd) {
    size_t id = (size_t)blockIdx.x * blockDim.x + threadIdx.x;
    if (id >= (size_t)UD * VD) return;
    __nv_bfloat16 b0, b1;
    split2(Wd[id], b0, b1);
    g_Wd0[id] = b0; g_Wd1[id] = b1;
}
__global__ void __launch_bounds__(256) prep_Wg_kernel(
    const float* __restrict__ Wx, const float* __restrict__ Wh) {
    int id = blockIdx.x * blockDim.x + threadIdx.x;
    if (id >= GK * ZN) return;
    int k = id >> 11, n = id & (ZN - 1);
    float v = (k < UD) ? Wx[(size_t)k * ZN + n] : Wh[(size_t)(k - UD) * ZN + n];
    __nv_bfloat16 b0, b1;
    split2(v, b0, b1);
    g_Wg0[id] = b0; g_Wg1[id] = b1;
}

// per-step gate A: concat(emb[idx], h_prev) split
__global__ void __launch_bounds__(256) gate_aprep_kernel(
    const float* __restrict__ h0, const float* __restrict__ emb, int t) {
    int id = blockIdx.x * blockDim.x + threadIdx.x;
    if (id >= NB * GK) return;
    int b = id >> 10, k = id & (GK - 1);
    float v;
    if (k < UD) {
        int idx = (t == 0) ? 1 : dec_idx(g_amax[b]);
        v = emb[(size_t)idx * UD + k];
    } else {
        v = ((t == 0) ? h0 : g_h)[b * UD + (k - UD)];
    }
    __nv_bfloat16 b0, b1;
    split2(v, b0, b1);
    g_Ag0[id] = b0; g_Ag1[id] = b1;
}

// ============================================================================
// GATE GEMM: z_part[ks] = A[64,256-chunk] @ Wg — grid (16 ntiles, 4 ksplits)
//   block tile 64x128, K-chunk 64 (4 chunks), cp.async double buffer.
// ============================================================================
#define GA_ST 144     // A smem row stride bytes (72 bf16)
#define GB_ST 272     // B smem row stride bytes (136 bf16)
#define GSA(buf, spl) (((buf) * 2 + (spl)) * 9216u)
#define GSB(buf, spl) (36864u + ((buf) * 2 + (spl)) * 17408u)
#define GSMEM (36864 + 69632)

__global__ void __launch_bounds__(256, 1) gate_mma_kernel() {
    extern __shared__ unsigned char smem[];
    const uint32_t smb = smem_u32(smem);
    const int tid = threadIdx.x, wid = tid >> 5, lane = tid & 31;
    const int wm = wid & 1, wn = wid >> 1;       // 2 x m32, 4 x n32
    const int n0 = blockIdx.x * 128;
    const int kbase = blockIdx.y * 256;

    const __nv_bfloat16* Asrc[2] = { g_Ag0, g_Ag1 };
    const __nv_bfloat16* Bsrc[2] = { g_Wg0, g_Wg1 };

    float acc[2][4][4];
#pragma unroll
    for (int i = 0; i < 2; i++)
#pragma unroll
        for (int j = 0; j < 4; j++)
#pragma unroll
            for (int q = 0; q < 4; q++) acc[i][j][q] = 0.f;

    auto load_chunk = [&](int ch, int buf) {
        int kc = kbase + ch * 64;
        // A: 2 spl * 64 rows * 8 (16B) = 1024 ops, 4/thread
#pragma unroll
        for (int j = 0; j < 4; j++) {
            int i = tid + j * 256;
            int s = i >> 9, rem = i & 511, r = rem >> 3, c8 = rem & 7;
            cp16(smb + GSA(buf, s) + r * GA_ST + c8 * 16,
                 Asrc[s] + (size_t)r * GK + kc + c8 * 8);
        }
        // B: 2 spl * 64 rows * 16 (16B) = 2048 ops, 8/thread
#pragma unroll
        for (int j = 0; j < 8; j++) {
            int i = tid + j * 256;
            int s = i >> 10, rem = i & 1023, r = rem >> 4, c16 = rem & 15;
            cp16(smb + GSB(buf, s) + r * GB_ST + c16 * 16,
                 Bsrc[s] + (size_t)(kc + r) * ZN + n0 + c16 * 8);
        }
        CP_COMMIT();
    };

    load_chunk(0, 0);
    for (int ch = 0; ch < 4; ch++) {
        if (ch < 3) load_chunk(ch + 1, (ch + 1) & 1);
        if (ch < 3) { CP_WAIT(1); } else { CP_WAIT(0); }
        __syncthreads();
        const int buf = ch & 1;
#pragma unroll
        for (int ks = 0; ks < 4; ks++) {
            uint32_t a0[2][4], a1[2][4];
#pragma unroll
            for (int mf = 0; mf < 2; mf++) {
                uint32_t arow = (wm * 32 + mf * 16 + (lane & 15)) * GA_ST
                              + ks * 32 + (lane >> 4) * 16;
                ldm_x4(a0[mf], smb + GSA(buf, 0) + arow);
                ldm_x4(a1[mf], smb + GSA(buf, 1) + arow);
            }
#pragma unroll
            for (int nt = 0; nt < 2; nt++) {
                uint32_t b0[4], b1[4];
                uint32_t boff = (ks * 16 + (lane & 15)) * GB_ST
                              + (wn * 32 + nt * 16) * 2 + (lane >> 4) * 16;
                ldm_x4t(b0, smb + GSB(buf, 0) + boff);
                ldm_x4t(b1, smb + GSB(buf, 1) + boff);
#pragma unroll
                for (int mf = 0; mf < 2; mf++) {
                    mma16816(acc[mf][nt * 2],     a0[mf], b0);
                    mma16816(acc[mf][nt * 2],     a1[mf], b0);
                    mma16816(acc[mf][nt * 2],     a0[mf], b1);
                    mma16816(acc[mf][nt * 2 + 1], a0[mf], b0 + 2);
                    mma16816(acc[mf][nt * 2 + 1], a1[mf], b0 + 2);
                    mma16816(acc[mf][nt * 2 + 1], a0[mf], b1 + 2);
                }
            }
        }
        __syncthreads();
    }

    float* zp = g_zpart[blockIdx.y];
#pragma unroll
    for (int mf = 0; mf < 2; mf++) {
#pragma unroll
        for (int nti = 0; nti < 4; nti++) {
            int r0 = wm * 32 + mf * 16 + (lane >> 2);
            int col = n0 + wn * 32 + nti * 8 + (lane & 3) * 2;
            *(float2*)&zp[(size_t)r0 * ZN + col] =
                make_float2(acc[mf][nti][0], acc[mf][nti][1]);
            *(float2*)&zp[(size_t)(r0 + 8) * ZN + col] =
                make_float2(acc[mf][nti][2], acc[mf][nti][3]);
        }
    }
}

// ============================================================================
// update: sum 4 partials + bias -> gates -> h,c; reset amax; emit h splits
// ============================================================================
__global__ void __launch_bounds__(256) lstm_update_kernel(
    const float* __restrict__ c0, const float* __restrict__ b_lstm, int t) {
    int id = blockIdx.x * blockDim.x + threadIdx.x;
    if (blockIdx.x == 0 && threadIdx.x < NB) g_amax[threadIdx.x] = 0ull;
    if (id >= NB * UD) return;
    int b = id / UD, u = id % UD;
    size_t base = (size_t)b * ZN;
    float zi = 0.f, zf = 0.f, zg = 0.f, zo = 0.f;
#pragma unroll
    for (int ks = 0; ks < GKS; ks++) {
        zi += g_zpart[ks][base + u];
        zf += g_zpart[ks][base + 512 + u];
        zg += g_zpart[ks][base + 1024 + u];
        zo += g_zpart[ks][base + 1536 + u];
    }
    zi += b_lstm[u];        zf += b_lstm[512 + u];
    zg += b_lstm[1024 + u]; zo += b_lstm[1536 + u];

    float cp = (t == 0) ? c0[id] : g_c[id];
    float si = 1.f / (1.f + expf(-zi));
    float sf = 1.f / (1.f + expf(-zf));
    float so = 1.f / (1.f + expf(-zo));
    float tg = tanhf(zg);
    float cn = sf * cp + si * tg;
    float hn = so * tanhf(cn);
    g_c[id] = cn;
    g_h[id] = hn;

    __nv_bfloat16 b0, b1;
    split2(hn, b0, b1);
    g_Al0[id] = b0; g_Al1[id] = b1;
}

// ============================================================================
// LOGITS GEMM: grid 125, block tile 64x256, K=512 in 8 chunks of 64.
// ============================================================================
#define LA_ST 144     // A row stride bytes (72 bf16)
#define LB_ST 528     // B row stride bytes (264 bf16)
#define LSA(buf, spl) (((buf) * 2 + (spl)) * 9216u)
#define LSB(buf, spl) (36864u + ((buf) * 2 + (spl)) * 33792u)
#define LSAMAX 172032
#define LSMEM (172032 + 512)

__global__ void __launch_bounds__(256, 1) logits_mma_kernel(
    const float* __restrict__ bd, float* __restrict__ out, int t) {
    extern __shared__ unsigned char smem[];
    const uint32_t smb = smem_u32(smem);
    unsigned long long* samax = (unsigned long long*)(smem + LSAMAX);
    const int tid = threadIdx.x, wid = tid >> 5, lane = tid & 31;
    const int wm = wid & 1, wn = wid >> 1;       // 2 x m32, 4 x n64
    const int v0 = blockIdx.x * 256;

    if (tid < NB) samax[tid] = 0ull;

    const __nv_bfloat16* Asrc[2] = { g_Al0, g_Al1 };
    const __nv_bfloat16* Bsrc[2] = { g_Wd0, g_Wd1 };

    float acc[2][8][4];
#pragma unroll
    for (int i = 0; i < 2; i++)
#pragma unroll
        for (int j = 0; j < 8; j++)
#pragma unroll
            for (int q = 0; q < 4; q++) acc[i][j][q] = 0.f;

    auto load_chunk = [&](int ch, int buf) {
        int kc = ch * 64;
        // A: 1024 ops, 4/thread
#pragma unroll
        for (int j = 0; j < 4; j++) {
            int i = tid + j * 256;
            int s = i >> 9, rem = i & 511, r = rem >> 3, c8 = rem & 7;
            cp16(smb + LSA(buf, s) + r * LA_ST + c8 * 16,
                 Asrc[s] + (size_t)r * UD + kc + c8 * 8);
        }
        // B: 2 spl * 64 rows * 32 (16B) = 4096 ops, 16/thread
#pragma unroll
        for (int j = 0; j < 16; j++) {
            int i = tid + j * 256;
            int s = i >> 11, rem = i & 2047, r = rem >> 5, c16 = rem & 31;
            cp16(smb + LSB(buf, s) + r * LB_ST + c16 * 16,
                 Bsrc[s] + (size_t)(kc + r) * VD + v0 + c16 * 8);
        }
        CP_COMMIT();
    };

    load_chunk(0, 0);
    for (int ch = 0; ch < 8; ch++) {
        if (ch < 7) load_chunk(ch + 1, (ch + 1) & 1);
        if (ch < 7) { CP_WAIT(1); } else { CP_WAIT(0); }
        __syncthreads();
        const int buf = ch & 1;
#pragma unroll
        for (int ks = 0; ks < 4; ks++) {
            uint32_t a0[2][4], a1[2][4];
#pragma unroll
            for (int mf = 0; mf < 2; mf++) {
                uint32_t arow = (wm * 32 + mf * 16 + (lane & 15)) * LA_ST
                              + ks * 32 + (lane >> 4) * 16;
                ldm_x4(a0[mf], smb + LSA(buf, 0) + arow);
                ldm_x4(a1[mf], smb + LSA(buf, 1) + arow);
            }
#pragma unroll
            for (int nt = 0; nt < 4; nt++) {
                uint32_t b0[4], b1[4];
                uint32_t boff = (ks * 16 + (lane & 15)) * LB_ST
                              + (wn * 64 + nt * 16) * 2 + (lane >> 4) * 16;
                ldm_x4t(b0, smb + LSB(buf, 0) + boff);
                ldm_x4t(b1, smb + LSB(buf, 1) + boff);
#pragma unroll
                for (int mf = 0; mf < 2; mf++) {
                    mma16816(acc[mf][nt * 2],     a0[mf], b0);
                    mma16816(acc[mf][nt * 2],     a1[mf], b0);
                    mma16816(acc[mf][nt * 2],     a0[mf], b1);
                    mma16816(acc[mf][nt * 2 + 1], a0[mf], b0 + 2);
                    mma16816(acc[mf][nt * 2 + 1], a1[mf], b0 + 2);
                    mma16816(acc[mf][nt * 2 + 1], a0[mf], b1 + 2);
                }
            }
        }
        __syncthreads();
    }

    // epilogue: bias, store, exact argmax
    unsigned long long best[2][2] = {{0ull, 0ull}, {0ull, 0ull}};
#pragma unroll
    for (int mf = 0; mf < 2; mf++) {
#pragma unroll
        for (int nti = 0; nti < 8; nti++) {
            int r0 = wm * 32 + mf * 16 + (lane >> 2);
            int col = v0 + wn * 64 + nti * 8 + (lane & 3) * 2;
            float2 bb = *(const float2*)&bd[col];
            float2 o0 = make_float2(acc[mf][nti][0] + bb.x, acc[mf][nti][1] + bb.y);
            float2 o1 = make_float2(acc[mf][nti][2] + bb.x, acc[mf][nti][3] + bb.y);
            *(float2*)&out[((size_t)r0 * TS + t) * VD + col] = o0;
            *(float2*)&out[((size_t)(r0 + 8) * TS + t) * VD + col] = o1;
            unsigned long long e;
            e = enc_max(o0.x, col);     if (e > best[mf][0]) best[mf][0] = e;
            e = enc_max(o0.y, col + 1); if (e > best[mf][0]) best[mf][0] = e;
            e = enc_max(o1.x, col);     if (e > best[mf][1]) best[mf][1] = e;
            e = enc_max(o1.y, col + 1); if (e > best[mf][1]) best[mf][1] = e;
        }
    }
    // reduce across the 4 lanes of each row quad
#pragma unroll
    for (int off = 1; off <= 2; off <<= 1) {
#pragma unroll
        for (int mf = 0; mf < 2; mf++)
#pragma unroll
            for (int h = 0; h < 2; h++) {
                unsigned long long o = __shfl_xor_sync(0xFFFFFFFFu, best[mf][h], off);
                if (o > best[mf][h]) best[mf][h] = o;
            }
    }
    if ((lane & 3) == 0) {
#pragma unroll
        for (int mf = 0; mf < 2; mf++)
#pragma unroll
            for (int h = 0; h < 2; h++) {
                int row = wm * 32 + mf * 16 + h * 8 + (lane >> 2);
                atomicMax(&samax[row], best[mf][h]);
            }
    }
    __syncthreads();
    if (tid < NB) atomicMax(&g_amax[tid], samax[tid]);
}

// ============================================================================
extern "C" void kernel_launch(void* const* d_in, const int* in_sizes, int n_in,
                              void* d_out, int out_size) {
    const float* h0  = (const float*)d_in[0];
    const float* c0  = (const float*)d_in[1];
    const float* emb = (const float*)d_in[2];
    const float* Wx  = (const float*)d_in[3];
    const float* Wh  = (const float*)d_in[4];
    const float* bl  = (const float*)d_in[5];
    const float* Wd  = (const float*)d_in[6];
    const float* bd  = (const float*)d_in[7];
    float* out = (float*)d_out;

    static bool attr_done = false;
    if (!attr_done) {
        cudaFuncSetAttribute(gate_mma_kernel,
                             cudaFuncAttributeMaxDynamicSharedMemorySize, GSMEM);
        cudaFuncSetAttribute(logits_mma_kernel,
                             cudaFuncAttributeMaxDynamicSharedMemorySize, LSMEM);
        attr_done = true;
    }

    prep_Wd_kernel<<<(int)(((size_t)UD * VD + 255) / 256), 256>>>(Wd);
    prep_Wg_kernel<<<(GK * ZN + 255) / 256, 256>>>(Wx, Wh);

    for (int t = 0; t < TS; t++) {
        gate_aprep_kernel<<<(NB * GK + 255) / 256, 256>>>(h0, emb, t);
        gate_mma_kernel<<<dim3(16, GKS), 256, GSMEM>>>();
        lstm_update_kernel<<<(NB * UD + 255) / 256, 256>>>(c0, bl, t);
        logits_mma_kernel<<<125, 256, LSMEM>>>(bd, out, t);
    }
}

// round 6
// speedup vs baseline: 5.0808x; 1.0605x over previous
#include <cuda_runtime.h>
#include <cuda_bf16.h>
#include <cstdint>

#define NB 64
#define UD 512
#define VD 32000
#define TS 20
#define ZN 2048
#define GK 1024
#define GKS 8          // gate K-splits (grid.y)

// ---------------- persistent device scratch ----------------
__device__ float g_h[NB * UD];
__device__ float g_c[NB * UD];
__device__ float g_zpart[GKS][NB * ZN];
__device__ unsigned long long g_amax[NB];
__device__ unsigned int g_barrier;   // monotonic ticket barrier (128/launch)
__device__ __nv_bfloat16 g_Wd0[(size_t)UD * VD];
__device__ __nv_bfloat16 g_Wd1[(size_t)UD * VD];
__device__ __nv_bfloat16 g_Wg0[(size_t)GK * ZN];
__device__ __nv_bfloat16 g_Wg1[(size_t)GK * ZN];
__device__ __nv_bfloat16 g_Al0[NB * UD];
__device__ __nv_bfloat16 g_Al1[NB * UD];

// ---------------- helpers ----------------
__device__ __forceinline__ unsigned long long enc_max(float v, int col) {
    unsigned int u = __float_as_uint(v);
    unsigned int key = (u & 0x80000000u) ? ~u : (u | 0x80000000u);
    return ((unsigned long long)key << 32) |
           (unsigned long long)(0xFFFFFFFFu - (unsigned int)col);
}
__device__ __forceinline__ int dec_idx(unsigned long long e) {
    return (int)(0xFFFFFFFFu - (unsigned int)(e & 0xFFFFFFFFull));
}
__device__ __forceinline__ void split2(float v, __nv_bfloat16& b0, __nv_bfloat16& b1) {
    b0 = __float2bfloat16(v);
    b1 = __float2bfloat16(v - __bfloat162float(b0));
}
__device__ __forceinline__ uint32_t smem_u32(const void* p) {
    uint32_t a;
    asm("{ .reg .u64 t; cvta.to.shared.u64 t, %1; cvt.u32.u64 %0, t; }"
        : "=r"(a) : "l"(p));
    return a;
}
__device__ __forceinline__ void cp16(uint32_t dst, const void* src) {
    asm volatile("cp.async.cg.shared.global [%0], [%1], 16;" :: "r"(dst), "l"(src));
}
#define CP_COMMIT() asm volatile("cp.async.commit_group;" ::: "memory")
#define CP_WAIT(n)  asm volatile("cp.async.wait_group %0;" :: "n"(n) : "memory")

__device__ __forceinline__ void ldm_x4(uint32_t* r, uint32_t addr) {
    asm volatile("ldmatrix.sync.aligned.m8n8.x4.shared.b16 {%0,%1,%2,%3}, [%4];"
        : "=r"(r[0]), "=r"(r[1]), "=r"(r[2]), "=r"(r[3]) : "r"(addr));
}
__device__ __forceinline__ void ldm_x4t(uint32_t* r, uint32_t addr) {
    asm volatile("ldmatrix.sync.aligned.m8n8.x4.trans.shared.b16 {%0,%1,%2,%3}, [%4];"
        : "=r"(r[0]), "=r"(r[1]), "=r"(r[2]), "=r"(r[3]) : "r"(addr));
}
__device__ __forceinline__ void mma16816(float* c, const uint32_t* a, const uint32_t* b) {
    asm volatile(
        "mma.sync.aligned.m16n8k16.row.col.f32.bf16.bf16.f32 "
        "{%0,%1,%2,%3}, {%4,%5,%6,%7}, {%8,%9}, {%0,%1,%2,%3};"
        : "+f"(c[0]), "+f"(c[1]), "+f"(c[2]), "+f"(c[3])
        : "r"(a[0]), "r"(a[1]), "r"(a[2]), "r"(a[3]), "r"(b[0]), "r"(b[1]));
}

// ============================================================================
// one-time weight splits (bf16 hi/lo), plain row-major
// ============================================================================
__global__ void __launch_bounds__(256) prep_Wd_kernel(const float* __restrict__ Wd) {
    size_t id = (size_t)blockIdx.x * blockDim.x + threadIdx.x;
    if (id >= (size_t)UD * VD) return;
    __nv_bfloat16 b0, b1;
    split2(Wd[id], b0, b1);
    g_Wd0[id] = b0; g_Wd1[id] = b1;
}
__global__ void __launch_bounds__(256) prep_Wg_kernel(
    const float* __restrict__ Wx, const float* __restrict__ Wh) {
    int id = blockIdx.x * blockDim.x + threadIdx.x;
    if (id >= GK * ZN) return;
    int k = id >> 11, n = id & (ZN - 1);
    float v = (k < UD) ? Wx[(size_t)k * ZN + n] : Wh[(size_t)(k - UD) * ZN + n];
    __nv_bfloat16 b0, b1;
    split2(v, b0, b1);
    g_Wg0[id] = b0; g_Wg1[id] = b1;
}

// ============================================================================
// STEP FRONT: fused gate GEMM + grid barrier + LSTM update.
//   grid (16 ntiles x 8 ksplits) = 128 blocks, 256 threads.
// ============================================================================
#define FA_ST 272     // A smem row stride bytes (136 bf16)
#define FB_ST 272     // B smem row stride bytes
#define FSA(spl)      ((spl) * 17408u)
#define FSB(buf, spl) (34816u + ((buf) * 2 + (spl)) * 17408u)
#define FSMEM (34816 + 69632)

__global__ void __launch_bounds__(256, 1) step_front_kernel(
    const float* __restrict__ h0, const float* __restrict__ c0,
    const float* __restrict__ emb, const float* __restrict__ b_lstm, int t)
{
    extern __shared__ unsigned char smem[];
    const uint32_t smb = smem_u32(smem);
    const int tid = threadIdx.x, wid = tid >> 5, lane = tid & 31;
    const int wm = wid & 1, wn = wid >> 1;       // 2 x m32, 4 x n32
    const int n0 = blockIdx.x * 128;
    const int ks = blockIdx.y;
    const int kbase = ks * 128;

    const __nv_bfloat16* Bsrc[2] = { g_Wg0, g_Wg1 };

    // ---- issue both B chunk loads up front (async) ----
    // each chunk: 2 splits * 64 K-rows * 16 (16B) = 2048 cp.async, 8/thread
#pragma unroll
    for (int ch = 0; ch < 2; ch++) {
        int kc = kbase + ch * 64;
#pragma unroll
        for (int j = 0; j < 8; j++) {
            int i = tid + j * 256;
            int s = i >> 10, rem = i & 1023, r = rem >> 4, c16 = rem & 15;
            cp16(smb + FSB(ch, s) + r * FB_ST + c16 * 16,
                 Bsrc[s] + (size_t)(kc + r) * ZN + n0 + c16 * 8);
        }
        CP_COMMIT();
    }

    // ---- A prep: gather fp32, split2, store bf16 to smem ----
    {
        const int row = tid >> 2;            // 64 rows, 4 threads/row
        const int cbase = (tid & 3) * 32;    // 32 cols/thread
        const float* src;
        if (ks < 4) {
            int idx = (t == 0) ? 1 : dec_idx(g_amax[row]);
            src = emb + (size_t)idx * UD + kbase + cbase;
        } else {
            const float* hp = (t == 0) ? h0 : g_h;
            src = hp + row * UD + (ks - 4) * 128 + cbase;
        }
        __nv_bfloat16* a0 = (__nv_bfloat16*)(smem + FSA(0) + row * FA_ST) + cbase;
        __nv_bfloat16* a1 = (__nv_bfloat16*)(smem + FSA(1) + row * FA_ST) + cbase;
#pragma unroll
        for (int q = 0; q < 8; q++) {
            float4 v = *(const float4*)(src + q * 4);
            __nv_bfloat16 lo, hi;
            split2(v.x, lo, hi); a0[q * 4 + 0] = lo; a1[q * 4 + 0] = hi;
            split2(v.y, lo, hi); a0[q * 4 + 1] = lo; a1[q * 4 + 1] = hi;
            split2(v.z, lo, hi); a0[q * 4 + 2] = lo; a1[q * 4 + 2] = hi;
            split2(v.w, lo, hi); a0[q * 4 + 3] = lo; a1[q * 4 + 3] = hi;
        }
    }

    float acc[2][4][4];
#pragma unroll
    for (int i = 0; i < 2; i++)
#pragma unroll
        for (int j = 0; j < 4; j++)
#pragma unroll
            for (int q = 0; q < 4; q++) acc[i][j][q] = 0.f;

#pragma unroll
    for (int ch = 0; ch < 2; ch++) {
        if (ch == 0) { CP_WAIT(1); } else { CP_WAIT(0); }
        __syncthreads();
#pragma unroll
        for (int kf = 0; kf < 4; kf++) {
            uint32_t a0[2][4], a1[2][4];
#pragma unroll
            for (int mf = 0; mf < 2; mf++) {
                uint32_t arow = (wm * 32 + mf * 16 + (lane & 15)) * FA_ST
                              + ch * 128 + kf * 32 + (lane >> 4) * 16;
                ldm_x4(a0[mf], smb + FSA(0) + arow);
                ldm_x4(a1[mf], smb + FSA(1) + arow);
            }
#pragma unroll
            for (int nt = 0; nt < 2; nt++) {
                uint32_t b0[4], b1[4];
                uint32_t boff = (kf * 16 + (lane & 15)) * FB_ST
                              + (wn * 32 + nt * 16) * 2 + (lane >> 4) * 16;
                ldm_x4t(b0, smb + FSB(ch, 0) + boff);
                ldm_x4t(b1, smb + FSB(ch, 1) + boff);
#pragma unroll
                for (int mf = 0; mf < 2; mf++) {
                    mma16816(acc[mf][nt * 2],     a0[mf], b0);
                    mma16816(acc[mf][nt * 2],     a1[mf], b0);
                    mma16816(acc[mf][nt * 2],     a0[mf], b1);
                    mma16816(acc[mf][nt * 2 + 1], a0[mf], b0 + 2);
                    mma16816(acc[mf][nt * 2 + 1], a1[mf], b0 + 2);
                    mma16816(acc[mf][nt * 2 + 1], a0[mf], b1 + 2);
                }
            }
        }
        if (ch == 0) __syncthreads();
    }

    // ---- store z partials ----
    float* zp = g_zpart[ks];
#pragma unroll
    for (int mf = 0; mf < 2; mf++) {
#pragma unroll
        for (int nti = 0; nti < 4; nti++) {
            int r0 = wm * 32 + mf * 16 + (lane >> 2);
            int col = n0 + wn * 32 + nti * 8 + (lane & 3) * 2;
            *(float2*)&zp[(size_t)r0 * ZN + col] =
                make_float2(acc[mf][nti][0], acc[mf][nti][1]);
            *(float2*)&zp[(size_t)(r0 + 8) * ZN + col] =
                make_float2(acc[mf][nti][2], acc[mf][nti][3]);
        }
    }

    // ---- grid barrier over the 128 co-resident blocks ----
    __threadfence();
    __syncthreads();
    if (tid == 0) {
        unsigned int ticket = atomicAdd(&g_barrier, 1u);
        unsigned int target = (ticket / 128u + 1u) * 128u;
        while (*(volatile unsigned int*)&g_barrier < target) __nanosleep(32);
        __threadfence();
    }
    __syncthreads();

    // ---- update phase: 1 element per thread (128 blk * 256 thr = 32768) ----
    {
        int blkLin = blockIdx.y * 16 + blockIdx.x;
        int id = blkLin * 256 + tid;
        int b = id >> 9, u = id & 511;
        size_t base = (size_t)b * ZN;
        float zi = 0.f, zf = 0.f, zg = 0.f, zo = 0.f;
#pragma unroll
        for (int s = 0; s < GKS; s++) {
            zi += __ldcg(&g_zpart[s][base + u]);
            zf += __ldcg(&g_zpart[s][base + 512 + u]);
            zg += __ldcg(&g_zpart[s][base + 1024 + u]);
            zo += __ldcg(&g_zpart[s][base + 1536 + u]);
        }
        zi += b_lstm[u];        zf += b_lstm[512 + u];
        zg += b_lstm[1024 + u]; zo += b_lstm[1536 + u];

        float cp = (t == 0) ? c0[id] : g_c[id];
        float si = 1.f / (1.f + expf(-zi));
        float sf = 1.f / (1.f + expf(-zf));
        float so = 1.f / (1.f + expf(-zo));
        float tg = tanhf(zg);
        float cn = sf * cp + si * tg;
        float hn = so * tanhf(cn);
        g_c[id] = cn;
        g_h[id] = hn;

        __nv_bfloat16 lo, hi;
        split2(hn, lo, hi);
        g_Al0[id] = lo; g_Al1[id] = hi;
        if (u == 0) g_amax[b] = 0ull;   // safe: all A-prep reads happened pre-barrier
    }
}

// ============================================================================
// LOGITS GEMM: grid 125, block tile 64x256, K=512 in 8 chunks of 64. (proven)
// ============================================================================
#define LA_ST 144
#define LB_ST 528
#define LSA(buf, spl) (((buf) * 2 + (spl)) * 9216u)
#define LSB(buf, spl) (36864u + ((buf) * 2 + (spl)) * 33792u)
#define LSAMAX 172032
#define LSMEM (172032 + 512)

__global__ void __launch_bounds__(256, 1) logits_mma_kernel(
    const float* __restrict__ bd, float* __restrict__ out, int t) {
    extern __shared__ unsigned char smem[];
    const uint32_t smb = smem_u32(smem);
    unsigned long long* samax = (unsigned long long*)(smem + LSAMAX);
    const int tid = threadIdx.x, wid = tid >> 5, lane = tid & 31;
    const int wm = wid & 1, wn = wid >> 1;
    const int v0 = blockIdx.x * 256;

    if (tid < NB) samax[tid] = 0ull;

    const __nv_bfloat16* Asrc[2] = { g_Al0, g_Al1 };
    const __nv_bfloat16* Bsrc[2] = { g_Wd0, g_Wd1 };

    float acc[2][8][4];
#pragma unroll
    for (int i = 0; i < 2; i++)
#pragma unroll
        for (int j = 0; j < 8; j++)
#pragma unroll
            for (int q = 0; q < 4; q++) acc[i][j][q] = 0.f;

    auto load_chunk = [&](int ch, int buf) {
        int kc = ch * 64;
#pragma unroll
        for (int j = 0; j < 4; j++) {
            int i = tid + j * 256;
            int s = i >> 9, rem = i & 511, r = rem >> 3, c8 = rem & 7;
            cp16(smb + LSA(buf, s) + r * LA_ST + c8 * 16,
                 Asrc[s] + (size_t)r * UD + kc + c8 * 8);
        }
#pragma unroll
        for (int j = 0; j < 16; j++) {
            int i = tid + j * 256;
            int s = i >> 11, rem = i & 2047, r = rem >> 5, c16 = rem & 31;
            cp16(smb + LSB(buf, s) + r * LB_ST + c16 * 16,
                 Bsrc[s] + (size_t)(kc + r) * VD + v0 + c16 * 8);
        }
        CP_COMMIT();
    };

    load_chunk(0, 0);
    for (int ch = 0; ch < 8; ch++) {
        if (ch < 7) load_chunk(ch + 1, (ch + 1) & 1);
        if (ch < 7) { CP_WAIT(1); } else { CP_WAIT(0); }
        __syncthreads();
        const int buf = ch & 1;
#pragma unroll
        for (int kf = 0; kf < 4; kf++) {
            uint32_t a0[2][4], a1[2][4];
#pragma unroll
            for (int mf = 0; mf < 2; mf++) {
                uint32_t arow = (wm * 32 + mf * 16 + (lane & 15)) * LA_ST
                              + kf * 32 + (lane >> 4) * 16;
                ldm_x4(a0[mf], smb + LSA(buf, 0) + arow);
                ldm_x4(a1[mf], smb + LSA(buf, 1) + arow);
            }
#pragma unroll
            for (int nt = 0; nt < 4; nt++) {
                uint32_t b0[4], b1[4];
                uint32_t boff = (kf * 16 + (lane & 15)) * LB_ST
                              + (wn * 64 + nt * 16) * 2 + (lane >> 4) * 16;
                ldm_x4t(b0, smb + LSB(buf, 0) + boff);
                ldm_x4t(b1, smb + LSB(buf, 1) + boff);
#pragma unroll
                for (int mf = 0; mf < 2; mf++) {
                    mma16816(acc[mf][nt * 2],     a0[mf], b0);
                    mma16816(acc[mf][nt * 2],     a1[mf], b0);
                    mma16816(acc[mf][nt * 2],     a0[mf], b1);
                    mma16816(acc[mf][nt * 2 + 1], a0[mf], b0 + 2);
                    mma16816(acc[mf][nt * 2 + 1], a1[mf], b0 + 2);
                    mma16816(acc[mf][nt * 2 + 1], a0[mf], b1 + 2);
                }
            }
        }
        __syncthreads();
    }

    unsigned long long best[2][2] = {{0ull, 0ull}, {0ull, 0ull}};
#pragma unroll
    for (int mf = 0; mf < 2; mf++) {
#pragma unroll
        for (int nti = 0; nti < 8; nti++) {
            int r0 = wm * 32 + mf * 16 + (lane >> 2);
            int col = v0 + wn * 64 + nti * 8 + (lane & 3) * 2;
            float2 bb = *(const float2*)&bd[col];
            float2 o0 = make_float2(acc[mf][nti][0] + bb.x, acc[mf][nti][1] + bb.y);
            float2 o1 = make_float2(acc[mf][nti][2] + bb.x, acc[mf][nti][3] + bb.y);
            *(float2*)&out[((size_t)r0 * TS + t) * VD + col] = o0;
            *(float2*)&out[((size_t)(r0 + 8) * TS + t) * VD + col] = o1;
            unsigned long long e;
            e = enc_max(o0.x, col);     if (e > best[mf][0]) best[mf][0] = e;
            e = enc_max(o0.y, col + 1); if (e > best[mf][0]) best[mf][0] = e;
            e = enc_max(o1.x, col);     if (e > best[mf][1]) best[mf][1] = e;
            e = enc_max(o1.y, col + 1); if (e > best[mf][1]) best[mf][1] = e;
        }
    }
#pragma unroll
    for (int off = 1; off <= 2; off <<= 1) {
#pragma unroll
        for (int mf = 0; mf < 2; mf++)
#pragma unroll
            for (int h = 0; h < 2; h++) {
                unsigned long long o = __shfl_xor_sync(0xFFFFFFFFu, best[mf][h], off);
                if (o > best[mf][h]) best[mf][h] = o;
            }
    }
    if ((lane & 3) == 0) {
#pragma unroll
        for (int mf = 0; mf < 2; mf++)
#pragma unroll
            for (int h = 0; h < 2; h++) {
                int row = wm * 32 + mf * 16 + h * 8 + (lane >> 2);
                atomicMax(&samax[row], best[mf][h]);
            }
    }
    __syncthreads();
    if (tid < NB) atomicMax(&g_amax[tid], samax[tid]);
}

// ============================================================================
extern "C" void kernel_launch(void* const* d_in, const int* in_sizes, int n_in,
                              void* d_out, int out_size) {
    const float* h0  = (const float*)d_in[0];
    const float* c0  = (const float*)d_in[1];
    const float* emb = (const float*)d_in[2];
    const float* Wx  = (const float*)d_in[3];
    const float* Wh  = (const float*)d_in[4];
    const float* bl  = (const float*)d_in[5];
    const float* Wd  = (const float*)d_in[6];
    const float* bd  = (const float*)d_in[7];
    float* out = (float*)d_out;

    static bool attr_done = false;
    if (!attr_done) {
        cudaFuncSetAttribute(step_front_kernel,
                             cudaFuncAttributeMaxDynamicSharedMemorySize, FSMEM);
        cudaFuncSetAttribute(logits_mma_kernel,
                             cudaFuncAttributeMaxDynamicSharedMemorySize, LSMEM);
        attr_done = true;
    }

    prep_Wd_kernel<<<(int)(((size_t)UD * VD + 255) / 256), 256>>>(Wd);
    prep_Wg_kernel<<<(GK * ZN + 255) / 256, 256>>>(Wx, Wh);

    for (int t = 0; t < TS; t++) {
        step_front_kernel<<<dim3(16, GKS), 256, FSMEM>>>(h0, c0, emb, bl, t);
        logits_mma_kernel<<<125, 256, LSMEM>>>(bd, out, t);
    }
}

// round 7
// speedup vs baseline: 5.1053x; 1.0048x over previous
#include <cuda_runtime.h>
#include <cuda_bf16.h>
#include <cstdint>

#define NB 64
#define UD 512
#define VD 32000
#define TS 20
#define ZN 2048
#define GK 1024
#define GKS 8          // gate K-splits (grid.y)

// ---------------- persistent device scratch ----------------
__device__ float g_h[NB * UD];
__device__ float g_c[NB * UD];
__device__ float g_zpart[GKS][NB * ZN];
__device__ unsigned long long g_amax[NB];
__device__ unsigned int g_barrier;   // monotonic ticket barrier (128/launch)
__device__ __nv_bfloat16 g_Wd0[(size_t)UD * VD];
__device__ __nv_bfloat16 g_Wd1[(size_t)UD * VD];
__device__ __nv_bfloat16 g_Wg0[(size_t)GK * ZN];
__device__ __nv_bfloat16 g_Wg1[(size_t)GK * ZN];
__device__ __nv_bfloat16 g_Al0[NB * UD];
__device__ __nv_bfloat16 g_Al1[NB * UD];

// ---------------- helpers ----------------
__device__ __forceinline__ unsigned long long enc_max(float v, int col) {
    unsigned int u = __float_as_uint(v);
    unsigned int key = (u & 0x80000000u) ? ~u : (u | 0x80000000u);
    return ((unsigned long long)key << 32) |
           (unsigned long long)(0xFFFFFFFFu - (unsigned int)col);
}
__device__ __forceinline__ int dec_idx(unsigned long long e) {
    return (int)(0xFFFFFFFFu - (unsigned int)(e & 0xFFFFFFFFull));
}
__device__ __forceinline__ void split2(float v, __nv_bfloat16& b0, __nv_bfloat16& b1) {
    b0 = __float2bfloat16(v);
    b1 = __float2bfloat16(v - __bfloat162float(b0));
}
__device__ __forceinline__ uint32_t smem_u32(const void* p) {
    uint32_t a;
    asm("{ .reg .u64 t; cvta.to.shared.u64 t, %1; cvt.u32.u64 %0, t; }"
        : "=r"(a) : "l"(p));
    return a;
}
__device__ __forceinline__ void cp16(uint32_t dst, const void* src) {
    asm volatile("cp.async.cg.shared.global [%0], [%1], 16;" :: "r"(dst), "l"(src));
}
// weight loads: bias L2 to keep Wd splits resident across all 20 steps
__device__ __forceinline__ uint64_t policy_evict_last() {
    uint64_t p;
    asm("createpolicy.fractional.L2::evict_last.b64 %0, 1.0;" : "=l"(p));
    return p;
}
__device__ __forceinline__ void cp16_el(uint32_t dst, const void* src, uint64_t pol) {
    asm volatile("cp.async.cg.shared.global.L2::cache_hint [%0], [%1], 16, %2;"
                 :: "r"(dst), "l"(src), "l"(pol));
}
#define CP_COMMIT() asm volatile("cp.async.commit_group;" ::: "memory")
#define CP_WAIT(n)  asm volatile("cp.async.wait_group %0;" :: "n"(n) : "memory")

__device__ __forceinline__ void ldm_x4(uint32_t* r, uint32_t addr) {
    asm volatile("ldmatrix.sync.aligned.m8n8.x4.shared.b16 {%0,%1,%2,%3}, [%4];"
        : "=r"(r[0]), "=r"(r[1]), "=r"(r[2]), "=r"(r[3]) : "r"(addr));
}
__device__ __forceinline__ void ldm_x4t(uint32_t* r, uint32_t addr) {
    asm volatile("ldmatrix.sync.aligned.m8n8.x4.trans.shared.b16 {%0,%1,%2,%3}, [%4];"
        : "=r"(r[0]), "=r"(r[1]), "=r"(r[2]), "=r"(r[3]) : "r"(addr));
}
__device__ __forceinline__ void mma16816(float* c, const uint32_t* a, const uint32_t* b) {
    asm volatile(
        "mma.sync.aligned.m16n8k16.row.col.f32.bf16.bf16.f32 "
        "{%0,%1,%2,%3}, {%4,%5,%6,%7}, {%8,%9}, {%0,%1,%2,%3};"
        : "+f"(c[0]), "+f"(c[1]), "+f"(c[2]), "+f"(c[3])
        : "r"(a[0]), "r"(a[1]), "r"(a[2]), "r"(a[3]), "r"(b[0]), "r"(b[1]));
}

// ============================================================================
// one-time weight splits (bf16 hi/lo), plain row-major
// ============================================================================
__global__ void __launch_bounds__(256) prep_Wd_kernel(const float* __restrict__ Wd) {
    size_t id = (size_t)blockIdx.x * blockDim.x + threadIdx.x;
    if (id >= (size_t)UD * VD) return;
    __nv_bfloat16 b0, b1;
    split2(Wd[id], b0, b1);
    g_Wd0[id] = b0; g_Wd1[id] = b1;
}
__global__ void __launch_bounds__(256) prep_Wg_kernel(
    const float* __restrict__ Wx, const float* __restrict__ Wh) {
    int id = blockIdx.x * blockDim.x + threadIdx.x;
    if (id >= GK * ZN) return;
    int k = id >> 11, n = id & (ZN - 1);
    float v = (k < UD) ? Wx[(size_t)k * ZN + n] : Wh[(size_t)(k - UD) * ZN + n];
    __nv_bfloat16 b0, b1;
    split2(v, b0, b1);
    g_Wg0[id] = b0; g_Wg1[id] = b1;
}

// ============================================================================
// STEP FRONT: fused gate GEMM + grid barrier + LSTM update. (proven R6)
//   grid (16 ntiles x 8 ksplits) = 128 blocks, 256 threads.
// ============================================================================
#define FA_ST 272
#define FB_ST 272
#define FSA(spl)      ((spl) * 17408u)
#define FSB(buf, spl) (34816u + ((buf) * 2 + (spl)) * 17408u)
#define FSMEM (34816 + 69632)

__global__ void __launch_bounds__(256, 1) step_front_kernel(
    const float* __restrict__ h0, const float* __restrict__ c0,
    const float* __restrict__ emb, const float* __restrict__ b_lstm, int t)
{
    extern __shared__ unsigned char smem[];
    const uint32_t smb = smem_u32(smem);
    const int tid = threadIdx.x, wid = tid >> 5, lane = tid & 31;
    const int wm = wid & 1, wn = wid >> 1;
    const int n0 = blockIdx.x * 128;
    const int ks = blockIdx.y;
    const int kbase = ks * 128;

    const __nv_bfloat16* Bsrc[2] = { g_Wg0, g_Wg1 };

#pragma unroll
    for (int ch = 0; ch < 2; ch++) {
        int kc = kbase + ch * 64;
#pragma unroll
        for (int j = 0; j < 8; j++) {
            int i = tid + j * 256;
            int s = i >> 10, rem = i & 1023, r = rem >> 4, c16 = rem & 15;
            cp16(smb + FSB(ch, s) + r * FB_ST + c16 * 16,
                 Bsrc[s] + (size_t)(kc + r) * ZN + n0 + c16 * 8);
        }
        CP_COMMIT();
    }

    {
        const int row = tid >> 2;
        const int cbase = (tid & 3) * 32;
        const float* src;
        if (ks < 4) {
            int idx = (t == 0) ? 1 : dec_idx(g_amax[row]);
            src = emb + (size_t)idx * UD + kbase + cbase;
        } else {
            const float* hp = (t == 0) ? h0 : g_h;
            src = hp + row * UD + (ks - 4) * 128 + cbase;
        }
        __nv_bfloat16* a0 = (__nv_bfloat16*)(smem + FSA(0) + row * FA_ST) + cbase;
        __nv_bfloat16* a1 = (__nv_bfloat16*)(smem + FSA(1) + row * FA_ST) + cbase;
#pragma unroll
        for (int q = 0; q < 8; q++) {
            float4 v = *(const float4*)(src + q * 4);
            __nv_bfloat16 lo, hi;
            split2(v.x, lo, hi); a0[q * 4 + 0] = lo; a1[q * 4 + 0] = hi;
            split2(v.y, lo, hi); a0[q * 4 + 1] = lo; a1[q * 4 + 1] = hi;
            split2(v.z, lo, hi); a0[q * 4 + 2] = lo; a1[q * 4 + 2] = hi;
            split2(v.w, lo, hi); a0[q * 4 + 3] = lo; a1[q * 4 + 3] = hi;
        }
    }

    float acc[2][4][4];
#pragma unroll
    for (int i = 0; i < 2; i++)
#pragma unroll
        for (int j = 0; j < 4; j++)
#pragma unroll
            for (int q = 0; q < 4; q++) acc[i][j][q] = 0.f;

#pragma unroll
    for (int ch = 0; ch < 2; ch++) {
        if (ch == 0) { CP_WAIT(1); } else { CP_WAIT(0); }
        __syncthreads();
#pragma unroll
        for (int kf = 0; kf < 4; kf++) {
            uint32_t a0[2][4], a1[2][4];
#pragma unroll
            for (int mf = 0; mf < 2; mf++) {
                uint32_t arow = (wm * 32 + mf * 16 + (lane & 15)) * FA_ST
                              + ch * 128 + kf * 32 + (lane >> 4) * 16;
                ldm_x4(a0[mf], smb + FSA(0) + arow);
                ldm_x4(a1[mf], smb + FSA(1) + arow);
            }
#pragma unroll
            for (int nt = 0; nt < 2; nt++) {
                uint32_t b0[4], b1[4];
                uint32_t boff = (kf * 16 + (lane & 15)) * FB_ST
                              + (wn * 32 + nt * 16) * 2 + (lane >> 4) * 16;
                ldm_x4t(b0, smb + FSB(ch, 0) + boff);
                ldm_x4t(b1, smb + FSB(ch, 1) + boff);
#pragma unroll
                for (int mf = 0; mf < 2; mf++) {
                    mma16816(acc[mf][nt * 2],     a0[mf], b0);
                    mma16816(acc[mf][nt * 2],     a1[mf], b0);
                    mma16816(acc[mf][nt * 2],     a0[mf], b1);
                    mma16816(acc[mf][nt * 2 + 1], a0[mf], b0 + 2);
                    mma16816(acc[mf][nt * 2 + 1], a1[mf], b0 + 2);
                    mma16816(acc[mf][nt * 2 + 1], a0[mf], b1 + 2);
                }
            }
        }
        if (ch == 0) __syncthreads();
    }

    float* zp = g_zpart[ks];
#pragma unroll
    for (int mf = 0; mf < 2; mf++) {
#pragma unroll
        for (int nti = 0; nti < 4; nti++) {
            int r0 = wm * 32 + mf * 16 + (lane >> 2);
            int col = n0 + wn * 32 + nti * 8 + (lane & 3) * 2;
            *(float2*)&zp[(size_t)r0 * ZN + col] =
                make_float2(acc[mf][nti][0], acc[mf][nti][1]);
            *(float2*)&zp[(size_t)(r0 + 8) * ZN + col] =
                make_float2(acc[mf][nti][2], acc[mf][nti][3]);
        }
    }

    __threadfence();
    __syncthreads();
    if (tid == 0) {
        unsigned int ticket = atomicAdd(&g_barrier, 1u);
        unsigned int target = (ticket / 128u + 1u) * 128u;
        while (*(volatile unsigned int*)&g_barrier < target) __nanosleep(32);
        __threadfence();
    }
    __syncthreads();

    {
        int blkLin = blockIdx.y * 16 + blockIdx.x;
        int id = blkLin * 256 + tid;
        int b = id >> 9, u = id & 511;
        size_t base = (size_t)b * ZN;
        float zi = 0.f, zf = 0.f, zg = 0.f, zo = 0.f;
#pragma unroll
        for (int s = 0; s < GKS; s++) {
            zi += __ldcg(&g_zpart[s][base + u]);
            zf += __ldcg(&g_zpart[s][base + 512 + u]);
            zg += __ldcg(&g_zpart[s][base + 1024 + u]);
            zo += __ldcg(&g_zpart[s][base + 1536 + u]);
        }
        zi += b_lstm[u];        zf += b_lstm[512 + u];
        zg += b_lstm[1024 + u]; zo += b_lstm[1536 + u];

        float cp = (t == 0) ? c0[id] : g_c[id];
        float si = 1.f / (1.f + expf(-zi));
        float sf = 1.f / (1.f + expf(-zf));
        float so = 1.f / (1.f + expf(-zo));
        float tg = tanhf(zg);
        float cn = sf * cp + si * tg;
        float hn = so * tanhf(cn);
        g_c[id] = cn;
        g_h[id] = hn;

        __nv_bfloat16 lo, hi;
        split2(hn, lo, hi);
        g_Al0[id] = lo; g_Al1[id] = hi;
        if (u == 0) g_amax[b] = 0ull;
    }
}

// ============================================================================
// LOGITS GEMM: grid 250, block tile 64x128 (2 blocks/SM), K=512 in 8 chunks.
//   Wd splits loaded with L2 evict_last hint; output stored streaming (.cs).
// ============================================================================
#define LA_ST 144
#define LB_ST 272
#define LSA(buf, spl) (((buf) * 2 + (spl)) * 9216u)
#define LSB(buf, spl) (36864u + ((buf) * 2 + (spl)) * 17408u)
#define LSAMAX (36864 + 69632)
#define LSMEM (LSAMAX + 512)

__global__ void __launch_bounds__(256, 2) logits_mma_kernel(
    const float* __restrict__ bd, float* __restrict__ out, int t) {
    extern __shared__ unsigned char smem[];
    const uint32_t smb = smem_u32(smem);
    unsigned long long* samax = (unsigned long long*)(smem + LSAMAX);
    const int tid = threadIdx.x, wid = tid >> 5, lane = tid & 31;
    const int wm = wid & 1, wn = wid >> 1;       // 2 x m32, 4 x n32
    const int v0 = blockIdx.x * 128;
    const uint64_t pol = policy_evict_last();

    if (tid < NB) samax[tid] = 0ull;

    const __nv_bfloat16* Asrc[2] = { g_Al0, g_Al1 };
    const __nv_bfloat16* Bsrc[2] = { g_Wd0, g_Wd1 };

    float acc[2][4][4];
#pragma unroll
    for (int i = 0; i < 2; i++)
#pragma unroll
        for (int j = 0; j < 4; j++)
#pragma unroll
            for (int q = 0; q < 4; q++) acc[i][j][q] = 0.f;

    auto load_chunk = [&](int ch, int buf) {
        int kc = ch * 64;
        // A: 2 spl * 64 rows * 8 (16B) = 1024 ops, 4/thread
#pragma unroll
        for (int j = 0; j < 4; j++) {
            int i = tid + j * 256;
            int s = i >> 9, rem = i & 511, r = rem >> 3, c8 = rem & 7;
            cp16(smb + LSA(buf, s) + r * LA_ST + c8 * 16,
                 Asrc[s] + (size_t)r * UD + kc + c8 * 8);
        }
        // B: 2 spl * 64 rows * 16 (16B) = 2048 ops, 8/thread, L2 evict_last
#pragma unroll
        for (int j = 0; j < 8; j++) {
            int i = tid + j * 256;
            int s = i >> 10, rem = i & 1023, r = rem >> 4, c16 = rem & 15;
            cp16_el(smb + LSB(buf, s) + r * LB_ST + c16 * 16,
                    Bsrc[s] + (size_t)(kc + r) * VD + v0 + c16 * 8, pol);
        }
        CP_COMMIT();
    };

    load_chunk(0, 0);
    for (int ch = 0; ch < 8; ch++) {
        if (ch < 7) load_chunk(ch + 1, (ch + 1) & 1);
        if (ch < 7) { CP_WAIT(1); } else { CP_WAIT(0); }
        __syncthreads();
        const int buf = ch & 1;
#pragma unroll
        for (int kf = 0; kf < 4; kf++) {
            uint32_t a0[2][4], a1[2][4];
#pragma unroll
            for (int mf = 0; mf < 2; mf++) {
                uint32_t arow = (wm * 32 + mf * 16 + (lane & 15)) * LA_ST
                              + kf * 32 + (lane >> 4) * 16;
                ldm_x4(a0[mf], smb + LSA(buf, 0) + arow);
                ldm_x4(a1[mf], smb + LSA(buf, 1) + arow);
            }
#pragma unroll
            for (int nt = 0; nt < 2; nt++) {
                uint32_t b0[4], b1[4];
                uint32_t boff = (kf * 16 + (lane & 15)) * LB_ST
                              + (wn * 32 + nt * 16) * 2 + (lane >> 4) * 16;
                ldm_x4t(b0, smb + LSB(buf, 0) + boff);
                ldm_x4t(b1, smb + LSB(buf, 1) + boff);
#pragma unroll
                for (int mf = 0; mf < 2; mf++) {
                    mma16816(acc[mf][nt * 2],     a0[mf], b0);
                    mma16816(acc[mf][nt * 2],     a1[mf], b0);
                    mma16816(acc[mf][nt * 2],     a0[mf], b1);
                    mma16816(acc[mf][nt * 2 + 1], a0[mf], b0 + 2);
                    mma16816(acc[mf][nt * 2 + 1], a1[mf], b0 + 2);
                    mma16816(acc[mf][nt * 2 + 1], a0[mf], b1 + 2);
                }
            }
        }
        __syncthreads();
    }

    // epilogue: bias, streaming store, exact argmax
    unsigned long long best[2][2] = {{0ull, 0ull}, {0ull, 0ull}};
#pragma unroll
    for (int mf = 0; mf < 2; mf++) {
#pragma unroll
        for (int nti = 0; nti < 4; nti++) {
            int r0 = wm * 32 + mf * 16 + (lane >> 2);
            int col = v0 + wn * 32 + nti * 8 + (lane & 3) * 2;
            float2 bb = *(const float2*)&bd[col];
            float2 o0 = make_float2(acc[mf][nti][0] + bb.x, acc[mf][nti][1] + bb.y);
            float2 o1 = make_float2(acc[mf][nti][2] + bb.x, acc[mf][nti][3] + bb.y);
            __stcs((float2*)&out[((size_t)r0 * TS + t) * VD + col], o0);
            __stcs((float2*)&out[((size_t)(r0 + 8) * TS + t) * VD + col], o1);
            unsigned long long e;
            e = enc_max(o0.x, col);     if (e > best[mf][0]) best[mf][0] = e;
            e = enc_max(o0.y, col + 1); if (e > best[mf][0]) best[mf][0] = e;
            e = enc_max(o1.x, col);     if (e > best[mf][1]) best[mf][1] = e;
            e = enc_max(o1.y, col + 1); if (e > best[mf][1]) best[mf][1] = e;
        }
    }
#pragma unroll
    for (int off = 1; off <= 2; off <<= 1) {
#pragma unroll
        for (int mf = 0; mf < 2; mf++)
#pragma unroll
            for (int h = 0; h < 2; h++) {
                unsigned long long o = __shfl_xor_sync(0xFFFFFFFFu, best[mf][h], off);
                if (o > best[mf][h]) best[mf][h] = o;
            }
    }
    if ((lane & 3) == 0) {
#pragma unroll
        for (int mf = 0; mf < 2; mf++)
#pragma unroll
            for (int h = 0; h < 2; h++) {
                int row = wm * 32 + mf * 16 + h * 8 + (lane >> 2);
                atomicMax(&samax[row], best[mf][h]);
            }
    }
    __syncthreads();
    if (tid < NB) atomicMax(&g_amax[tid], samax[tid]);
}

// ============================================================================
extern "C" void kernel_launch(void* const* d_in, const int* in_sizes, int n_in,
                              void* d_out, int out_size) {
    const float* h0  = (const float*)d_in[0];
    const float* c0  = (const float*)d_in[1];
    const float* emb = (const float*)d_in[2];
    const float* Wx  = (const float*)d_in[3];
    const float* Wh  = (const float*)d_in[4];
    const float* bl  = (const float*)d_in[5];
    const float* Wd  = (const float*)d_in[6];
    const float* bd  = (const float*)d_in[7];
    float* out = (float*)d_out;

    static bool attr_done = false;
    if (!attr_done) {
        cudaFuncSetAttribute(step_front_kernel,
                             cudaFuncAttributeMaxDynamicSharedMemorySize, FSMEM);
        cudaFuncSetAttribute(logits_mma_kernel,
                             cudaFuncAttributeMaxDynamicSharedMemorySize, LSMEM);
        attr_done = true;
    }

    prep_Wd_kernel<<<(int)(((size_t)UD * VD + 255) / 256), 256>>>(Wd);
    prep_Wg_kernel<<<(GK * ZN + 255) / 256, 256>>>(Wx, Wh);

    for (int t = 0; t < TS; t++) {
        step_front_kernel<<<dim3(16, GKS), 256, FSMEM>>>(h0, c0, emb, bl, t);
        logits_mma_kernel<<<250, 256, LSMEM>>>(bd, out, t);
    }
}

// round 8
// speedup vs baseline: 5.3473x; 1.0474x over previous
#include <cuda_runtime.h>
#include <cuda_bf16.h>
#include <cstdint>

#define NB 64
#define UD 512
#define VD 32000
#define TS 20
#define ZN 2048
#define GK 1024
#define GKS 8          // gate K-splits (grid.y)

// ---------------- persistent device scratch ----------------
__device__ float g_h[NB * UD];
__device__ float g_c[NB * UD];
__device__ float g_zpart[GKS][NB * ZN];
__device__ unsigned long long g_amax[NB];
__device__ unsigned int g_barrier;   // monotonic ticket barrier (128/launch)
__device__ __nv_bfloat16 g_Wd0[(size_t)UD * VD];
__device__ __nv_bfloat16 g_Wd1[(size_t)UD * VD];
__device__ __nv_bfloat16 g_Wg0[(size_t)GK * ZN];
__device__ __nv_bfloat16 g_Wg1[(size_t)GK * ZN];
__device__ __nv_bfloat16 g_Al0[NB * UD];
__device__ __nv_bfloat16 g_Al1[NB * UD];

// ---------------- helpers ----------------
__device__ __forceinline__ unsigned long long enc_max(float v, int col) {
    unsigned int u = __float_as_uint(v);
    unsigned int key = (u & 0x80000000u) ? ~u : (u | 0x80000000u);
    return ((unsigned long long)key << 32) |
           (unsigned long long)(0xFFFFFFFFu - (unsigned int)col);
}
__device__ __forceinline__ int dec_idx(unsigned long long e) {
    return (int)(0xFFFFFFFFu - (unsigned int)(e & 0xFFFFFFFFull));
}
__device__ __forceinline__ void split2(float v, __nv_bfloat16& b0, __nv_bfloat16& b1) {
    b0 = __float2bfloat16(v);
    b1 = __float2bfloat16(v - __bfloat162float(b0));
}
__device__ __forceinline__ uint32_t smem_u32(const void* p) {
    uint32_t a;
    asm("{ .reg .u64 t; cvta.to.shared.u64 t, %1; cvt.u32.u64 %0, t; }"
        : "=r"(a) : "l"(p));
    return a;
}
__device__ __forceinline__ void cp16(uint32_t dst, const void* src) {
    asm volatile("cp.async.cg.shared.global [%0], [%1], 16;" :: "r"(dst), "l"(src));
}
__device__ __forceinline__ uint64_t policy_evict_last() {
    uint64_t p;
    asm("createpolicy.fractional.L2::evict_last.b64 %0, 1.0;" : "=l"(p));
    return p;
}
__device__ __forceinline__ void cp16_el(uint32_t dst, const void* src, uint64_t pol) {
    asm volatile("cp.async.cg.shared.global.L2::cache_hint [%0], [%1], 16, %2;"
                 :: "r"(dst), "l"(src), "l"(pol));
}
#define CP_COMMIT() asm volatile("cp.async.commit_group;" ::: "memory")
#define CP_WAIT(n)  asm volatile("cp.async.wait_group %0;" :: "n"(n) : "memory")

__device__ __forceinline__ void ldm_x4(uint32_t* r, uint32_t addr) {
    asm volatile("ldmatrix.sync.aligned.m8n8.x4.shared.b16 {%0,%1,%2,%3}, [%4];"
        : "=r"(r[0]), "=r"(r[1]), "=r"(r[2]), "=r"(r[3]) : "r"(addr));
}
__device__ __forceinline__ void ldm_x4t(uint32_t* r, uint32_t addr) {
    asm volatile("ldmatrix.sync.aligned.m8n8.x4.trans.shared.b16 {%0,%1,%2,%3}, [%4];"
        : "=r"(r[0]), "=r"(r[1]), "=r"(r[2]), "=r"(r[3]) : "r"(addr));
}
__device__ __forceinline__ void mma16816(float* c, const uint32_t* a, const uint32_t* b) {
    asm volatile(
        "mma.sync.aligned.m16n8k16.row.col.f32.bf16.bf16.f32 "
        "{%0,%1,%2,%3}, {%4,%5,%6,%7}, {%8,%9}, {%0,%1,%2,%3};"
        : "+f"(c[0]), "+f"(c[1]), "+f"(c[2]), "+f"(c[3])
        : "r"(a[0]), "r"(a[1]), "r"(a[2]), "r"(a[3]), "r"(b[0]), "r"(b[1]));
}

// ============================================================================
// one-time weight splits (bf16 hi/lo), plain row-major
// ============================================================================
__global__ void __launch_bounds__(256) prep_Wd_kernel(const float* __restrict__ Wd) {
    size_t id = (size_t)blockIdx.x * blockDim.x + threadIdx.x;
    if (id >= (size_t)UD * VD) return;
    __nv_bfloat16 b0, b1;
    split2(Wd[id], b0, b1);
    g_Wd0[id] = b0; g_Wd1[id] = b1;
}
__global__ void __launch_bounds__(256) prep_Wg_kernel(
    const float* __restrict__ Wx, const float* __restrict__ Wh) {
    int id = blockIdx.x * blockDim.x + threadIdx.x;
    if (id >= GK * ZN) return;
    int k = id >> 11, n = id & (ZN - 1);
    float v = (k < UD) ? Wx[(size_t)k * ZN + n] : Wh[(size_t)(k - UD) * ZN + n];
    __nv_bfloat16 b0, b1;
    split2(v, b0, b1);
    g_Wg0[id] = b0; g_Wg1[id] = b1;
}

// ============================================================================
// STEP FRONT: fused gate GEMM + grid barrier + LSTM update. (proven R6/R7)
// ============================================================================
#define FA_ST 272
#define FB_ST 272
#define FSA(spl)      ((spl) * 17408u)
#define FSB(buf, spl) (34816u + ((buf) * 2 + (spl)) * 17408u)
#define FSMEM (34816 + 69632)

__global__ void __launch_bounds__(256, 1) step_front_kernel(
    const float* __restrict__ h0, const float* __restrict__ c0,
    const float* __restrict__ emb, const float* __restrict__ b_lstm, int t)
{
    extern __shared__ unsigned char smem[];
    const uint32_t smb = smem_u32(smem);
    const int tid = threadIdx.x, wid = tid >> 5, lane = tid & 31;
    const int wm = wid & 1, wn = wid >> 1;
    const int n0 = blockIdx.x * 128;
    const int ks = blockIdx.y;
    const int kbase = ks * 128;

    const __nv_bfloat16* Bsrc[2] = { g_Wg0, g_Wg1 };

#pragma unroll
    for (int ch = 0; ch < 2; ch++) {
        int kc = kbase + ch * 64;
#pragma unroll
        for (int j = 0; j < 8; j++) {
            int i = tid + j * 256;
            int s = i >> 10, rem = i & 1023, r = rem >> 4, c16 = rem & 15;
            cp16(smb + FSB(ch, s) + r * FB_ST + c16 * 16,
                 Bsrc[s] + (size_t)(kc + r) * ZN + n0 + c16 * 8);
        }
        CP_COMMIT();
    }

    {
        const int row = tid >> 2;
        const int cbase = (tid & 3) * 32;
        const float* src;
        if (ks < 4) {
            int idx = (t == 0) ? 1 : dec_idx(g_amax[row]);
            src = emb + (size_t)idx * UD + kbase + cbase;
        } else {
            const float* hp = (t == 0) ? h0 : g_h;
            src = hp + row * UD + (ks - 4) * 128 + cbase;
        }
        __nv_bfloat16* a0 = (__nv_bfloat16*)(smem + FSA(0) + row * FA_ST) + cbase;
        __nv_bfloat16* a1 = (__nv_bfloat16*)(smem + FSA(1) + row * FA_ST) + cbase;
#pragma unroll
        for (int q = 0; q < 8; q++) {
            float4 v = *(const float4*)(src + q * 4);
            __nv_bfloat16 lo, hi;
            split2(v.x, lo, hi); a0[q * 4 + 0] = lo; a1[q * 4 + 0] = hi;
            split2(v.y, lo, hi); a0[q * 4 + 1] = lo; a1[q * 4 + 1] = hi;
            split2(v.z, lo, hi); a0[q * 4 + 2] = lo; a1[q * 4 + 2] = hi;
            split2(v.w, lo, hi); a0[q * 4 + 3] = lo; a1[q * 4 + 3] = hi;
        }
    }

    float acc[2][4][4];
#pragma unroll
    for (int i = 0; i < 2; i++)
#pragma unroll
        for (int j = 0; j < 4; j++)
#pragma unroll
            for (int q = 0; q < 4; q++) acc[i][j][q] = 0.f;

#pragma unroll
    for (int ch = 0; ch < 2; ch++) {
        if (ch == 0) { CP_WAIT(1); } else { CP_WAIT(0); }
        __syncthreads();
#pragma unroll
        for (int kf = 0; kf < 4; kf++) {
            uint32_t a0[2][4], a1[2][4];
#pragma unroll
            for (int mf = 0; mf < 2; mf++) {
                uint32_t arow = (wm * 32 + mf * 16 + (lane & 15)) * FA_ST
                              + ch * 128 + kf * 32 + (lane >> 4) * 16;
                ldm_x4(a0[mf], smb + FSA(0) + arow);
                ldm_x4(a1[mf], smb + FSA(1) + arow);
            }
#pragma unroll
            for (int nt = 0; nt < 2; nt++) {
                uint32_t b0[4], b1[4];
                uint32_t boff = (kf * 16 + (lane & 15)) * FB_ST
                              + (wn * 32 + nt * 16) * 2 + (lane >> 4) * 16;
                ldm_x4t(b0, smb + FSB(ch, 0) + boff);
                ldm_x4t(b1, smb + FSB(ch, 1) + boff);
#pragma unroll
                for (int mf = 0; mf < 2; mf++) {
                    mma16816(acc[mf][nt * 2],     a0[mf], b0);
                    mma16816(acc[mf][nt * 2],     a1[mf], b0);
                    mma16816(acc[mf][nt * 2],     a0[mf], b1);
                    mma16816(acc[mf][nt * 2 + 1], a0[mf], b0 + 2);
                    mma16816(acc[mf][nt * 2 + 1], a1[mf], b0 + 2);
                    mma16816(acc[mf][nt * 2 + 1], a0[mf], b1 + 2);
                }
            }
        }
        if (ch == 0) __syncthreads();
    }

    float* zp = g_zpart[ks];
#pragma unroll
    for (int mf = 0; mf < 2; mf++) {
#pragma unroll
        for (int nti = 0; nti < 4; nti++) {
            int r0 = wm * 32 + mf * 16 + (lane >> 2);
            int col = n0 + wn * 32 + nti * 8 + (lane & 3) * 2;
            *(float2*)&zp[(size_t)r0 * ZN + col] =
                make_float2(acc[mf][nti][0], acc[mf][nti][1]);
            *(float2*)&zp[(size_t)(r0 + 8) * ZN + col] =
                make_float2(acc[mf][nti][2], acc[mf][nti][3]);
        }
    }

    __threadfence();
    __syncthreads();
    if (tid == 0) {
        unsigned int ticket = atomicAdd(&g_barrier, 1u);
        unsigned int target = (ticket / 128u + 1u) * 128u;
        while (*(volatile unsigned int*)&g_barrier < target) __nanosleep(32);
        __threadfence();
    }
    __syncthreads();

    {
        int blkLin = blockIdx.y * 16 + blockIdx.x;
        int id = blkLin * 256 + tid;
        int b = id >> 9, u = id & 511;
        size_t base = (size_t)b * ZN;
        float zi = 0.f, zf = 0.f, zg = 0.f, zo = 0.f;
#pragma unroll
        for (int s = 0; s < GKS; s++) {
            zi += __ldcg(&g_zpart[s][base + u]);
            zf += __ldcg(&g_zpart[s][base + 512 + u]);
            zg += __ldcg(&g_zpart[s][base + 1024 + u]);
            zo += __ldcg(&g_zpart[s][base + 1536 + u]);
        }
        zi += b_lstm[u];        zf += b_lstm[512 + u];
        zg += b_lstm[1024 + u]; zo += b_lstm[1536 + u];

        float cp = (t == 0) ? c0[id] : g_c[id];
        float si = 1.f / (1.f + expf(-zi));
        float sf = 1.f / (1.f + expf(-zf));
        float so = 1.f / (1.f + expf(-zo));
        float tg = tanhf(zg);
        float cn = sf * cp + si * tg;
        float hn = so * tanhf(cn);
        g_c[id] = cn;
        g_h[id] = hn;

        __nv_bfloat16 lo, hi;
        split2(hn, lo, hi);
        g_Al0[id] = lo; g_Al1[id] = hi;
        if (u == 0) g_amax[b] = 0ull;
    }
}

// ============================================================================
// LOGITS GEMM: grid 250, tile 64x128, K=512 in 16 chunks of 32, 4-stage
//   cp.async pipeline (3 chunks in flight). v0 order reversed on odd steps.
// ============================================================================
#define LA_ST 80      // A smem row stride (32 bf16 + pad) — conflict-free ldm
#define LB_ST 272     // B smem row stride (128 bf16 + pad)
#define LSA(st, spl) (((st) * 2 + (spl)) * 5120u)
#define LSB(st, spl) (40960u + ((st) * 2 + (spl)) * 8704u)
#define LSAMAX 110592
#define LSMEM (LSAMAX + 512)

__global__ void __launch_bounds__(256, 2) logits_mma_kernel(
    const float* __restrict__ bd, float* __restrict__ out, int t) {
    extern __shared__ unsigned char smem[];
    const uint32_t smb = smem_u32(smem);
    unsigned long long* samax = (unsigned long long*)(smem + LSAMAX);
    const int tid = threadIdx.x, wid = tid >> 5, lane = tid & 31;
    const int wm = wid & 1, wn = wid >> 1;       // 2 x m32, 4 x n32
    const int nt_idx = (t & 1) ? (249 - (int)blockIdx.x) : (int)blockIdx.x;
    const int v0 = nt_idx * 128;
    const uint64_t pol = policy_evict_last();

    if (tid < NB) samax[tid] = 0ull;

    const __nv_bfloat16* Asrc[2] = { g_Al0, g_Al1 };
    const __nv_bfloat16* Bsrc[2] = { g_Wd0, g_Wd1 };

    float acc[2][4][4];
#pragma unroll
    for (int i = 0; i < 2; i++)
#pragma unroll
        for (int j = 0; j < 4; j++)
#pragma unroll
            for (int q = 0; q < 4; q++) acc[i][j][q] = 0.f;

    auto load_chunk = [&](int ch, int st) {
        int kc = ch * 32;
        // A: 2 spl * 64 rows * 4 (16B) = 512 ops, 2/thread
#pragma unroll
        for (int j = 0; j < 2; j++) {
            int i = tid + j * 256;
            int s = i >> 8, rem = i & 255, r = rem >> 2, c4 = rem & 3;
            cp16(smb + LSA(st, s) + r * LA_ST + c4 * 16,
                 Asrc[s] + (size_t)r * UD + kc + c4 * 8);
        }
        // B: 2 spl * 32 rows * 16 (16B) = 1024 ops, 4/thread
#pragma unroll
        for (int j = 0; j < 4; j++) {
            int i = tid + j * 256;
            int s = i >> 9, rem = i & 511, r = rem >> 4, c16 = rem & 15;
            cp16_el(smb + LSB(st, s) + r * LB_ST + c16 * 16,
                    Bsrc[s] + (size_t)(kc + r) * VD + v0 + c16 * 8, pol);
        }
        CP_COMMIT();
    };

    load_chunk(0, 0);
    load_chunk(1, 1);
    load_chunk(2, 2);

#pragma unroll
    for (int ch = 0; ch < 16; ch++) {
        if (ch + 3 < 16) { load_chunk(ch + 3, (ch + 3) & 3); CP_WAIT(3); }
        else if (ch == 13) { CP_WAIT(2); }
        else if (ch == 14) { CP_WAIT(1); }
        else               { CP_WAIT(0); }
        __syncthreads();
        const int st = ch & 3;
#pragma unroll
        for (int kf = 0; kf < 2; kf++) {
            uint32_t a0[2][4], a1[2][4];
#pragma unroll
            for (int mf = 0; mf < 2; mf++) {
                uint32_t arow = (wm * 32 + mf * 16 + (lane & 15)) * LA_ST
                              + kf * 32 + (lane >> 4) * 16;
                ldm_x4(a0[mf], smb + LSA(st, 0) + arow);
                ldm_x4(a1[mf], smb + LSA(st, 1) + arow);
            }
#pragma unroll
            for (int nt = 0; nt < 2; nt++) {
                uint32_t b0[4], b1[4];
                uint32_t boff = (kf * 16 + (lane & 15)) * LB_ST
                              + (wn * 32 + nt * 16) * 2 + (lane >> 4) * 16;
                ldm_x4t(b0, smb + LSB(st, 0) + boff);
                ldm_x4t(b1, smb + LSB(st, 1) + boff);
#pragma unroll
                for (int mf = 0; mf < 2; mf++) {
                    mma16816(acc[mf][nt * 2],     a0[mf], b0);
                    mma16816(acc[mf][nt * 2],     a1[mf], b0);
                    mma16816(acc[mf][nt * 2],     a0[mf], b1);
                    mma16816(acc[mf][nt * 2 + 1], a0[mf], b0 + 2);
                    mma16816(acc[mf][nt * 2 + 1], a1[mf], b0 + 2);
                    mma16816(acc[mf][nt * 2 + 1], a0[mf], b1 + 2);
                }
            }
        }
        __syncthreads();
    }

    // epilogue: bias, streaming store, exact argmax
    unsigned long long best[2][2] = {{0ull, 0ull}, {0ull, 0ull}};
#pragma unroll
    for (int mf = 0; mf < 2; mf++) {
#pragma unroll
        for (int nti = 0; nti < 4; nti++) {
            int r0 = wm * 32 + mf * 16 + (lane >> 2);
            int col = v0 + wn * 32 + nti * 8 + (lane & 3) * 2;
            float2 bb = *(const float2*)&bd[col];
            float2 o0 = make_float2(acc[mf][nti][0] + bb.x, acc[mf][nti][1] + bb.y);
            float2 o1 = make_float2(acc[mf][nti][2] + bb.x, acc[mf][nti][3] + bb.y);
            __stcs((float2*)&out[((size_t)r0 * TS + t) * VD + col], o0);
            __stcs((float2*)&out[((size_t)(r0 + 8) * TS + t) * VD + col], o1);
            unsigned long long e;
            e = enc_max(o0.x, col);     if (e > best[mf][0]) best[mf][0] = e;
            e = enc_max(o0.y, col + 1); if (e > best[mf][0]) best[mf][0] = e;
            e = enc_max(o1.x, col);     if (e > best[mf][1]) best[mf][1] = e;
            e = enc_max(o1.y, col + 1); if (e > best[mf][1]) best[mf][1] = e;
        }
    }
#pragma unroll
    for (int off = 1; off <= 2; off <<= 1) {
#pragma unroll
        for (int mf = 0; mf < 2; mf++)
#pragma unroll
            for (int h = 0; h < 2; h++) {
                unsigned long long o = __shfl_xor_sync(0xFFFFFFFFu, best[mf][h], off);
                if (o > best[mf][h]) best[mf][h] = o;
            }
    }
    if ((lane & 3) == 0) {
#pragma unroll
        for (int mf = 0; mf < 2; mf++)
#pragma unroll
            for (int h = 0; h < 2; h++) {
                int row = wm * 32 + mf * 16 + h * 8 + (lane >> 2);
                atomicMax(&samax[row], best[mf][h]);
            }
    }
    __syncthreads();
    if (tid < NB) atomicMax(&g_amax[tid], samax[tid]);
}

// ============================================================================
extern "C" void kernel_launch(void* const* d_in, const int* in_sizes, int n_in,
                              void* d_out, int out_size) {
    const float* h0  = (const float*)d_in[0];
    const float* c0  = (const float*)d_in[1];
    const float* emb = (const float*)d_in[2];
    const float* Wx  = (const float*)d_in[3];
    const float* Wh  = (const float*)d_in[4];
    const float* bl  = (const float*)d_in[5];
    const float* Wd  = (const float*)d_in[6];
    const float* bd  = (const float*)d_in[7];
    float* out = (float*)d_out;

    static bool attr_done = false;
    if (!attr_done) {
        cudaFuncSetAttribute(step_front_kernel,
                             cudaFuncAttributeMaxDynamicSharedMemorySize, FSMEM);
        cudaFuncSetAttribute(logits_mma_kernel,
                             cudaFuncAttributeMaxDynamicSharedMemorySize, LSMEM);
        attr_done = true;
    }

    prep_Wd_kernel<<<(int)(((size_t)UD * VD + 255) / 256), 256>>>(Wd);
    prep_Wg_kernel<<<(GK * ZN + 255) / 256, 256>>>(Wx, Wh);

    for (int t = 0; t < TS; t++) {
        step_front_kernel<<<dim3(16, GKS), 256, FSMEM>>>(h0, c0, emb, bl, t);
        logits_mma_kernel<<<250, 256, LSMEM>>>(bd, out, t);
    }
}